// round 1
// baseline (speedup 1.0000x reference)
#include <cuda_runtime.h>
#include <cstdint>
#include <cstddef>

#define BB   32
#define SS   1024
#define HH   256
#define G4   1024          // 4*H
#define NBLK_DIR 64        // blocks per direction in recurrent kernel
#define HPAD 260           // padded row stride (floats) for shared h/w

#define HN_OFF (32ull*1024ull*512ull)            // 16777216
#define CN_OFF (HN_OFF + 2ull*32ull*512ull)      // +32768

// ---------------- device scratch (no cudaMalloc allowed) ----------------
__device__ float g_xproj[2][SS*BB][G4];   // [dir][s*32+b][gate]  268MB (reused across layers)
__device__ float g_out0[SS*BB][512];      // layer0 output [s*32+b][ch]
__device__ float g_h[2][BB][HH];          // per-dir hidden state
__device__ int   g_cnt[2][2][SS];         // [layer][dir][step] barrier counters

// ---------------- reset barrier counters (runs each replay) -------------
__global__ void reset_kernel() {
    int i = blockIdx.x * blockDim.x + threadIdx.x;
    if (i < 2 * 2 * SS) ((int*)g_cnt)[i] = 0;
}

// ---------------- input projection GEMM ---------------------------------
// out[dir][m][g] = sum_k X(m,k) * W_dir[g][k] + bih[g] + bhh[g]
// m = s*32+b.  layer0: X(m,k) = inputs[b][s][k]. layer1: X(m,k) = g_out0[m][k].
// BM=128, BN=64, BK=16, 256 threads, 8x4 per thread.
__global__ void __launch_bounds__(256) xproj_kernel(
    const float* __restrict__ xin, int layer, int K,
    const float* __restrict__ Wf, const float* __restrict__ Wb,
    const float* __restrict__ bihf, const float* __restrict__ bhhf,
    const float* __restrict__ bihb, const float* __restrict__ bhhb)
{
    __shared__ float As[16][128];
    __shared__ float Bs[16][64];
    const int dir = blockIdx.z;
    const float* W  = dir ? Wb   : Wf;
    const float* bi = dir ? bihb : bihf;
    const float* bh = dir ? bhhb : bhhf;
    const float* X  = (layer == 0) ? xin : &g_out0[0][0];
    const int m0 = blockIdx.y * 128;
    const int n0 = blockIdx.x * 64;
    const int tid = threadIdx.x;
    const int ty = tid >> 4, tx = tid & 15;

    float acc[8][4];
    #pragma unroll
    for (int i = 0; i < 8; i++)
        #pragma unroll
        for (int j = 0; j < 4; j++) acc[i][j] = 0.f;

    for (int k0 = 0; k0 < K; k0 += 16) {
        // load A tile (128 rows x 16 k) into As[k][m]
        #pragma unroll
        for (int jj = 0; jj < 2; jj++) {
            int idx = tid * 2 + jj;
            int row = idx >> 2;
            int kk  = (idx & 3) << 2;
            int m = m0 + row;
            const float* ap;
            if (layer == 0) {
                int s = m >> 5, b = m & 31;
                ap = X + ((size_t)b * SS + s) * 256 + k0 + kk;
            } else {
                ap = X + (size_t)m * 512 + k0 + kk;
            }
            float4 v = *(const float4*)ap;
            As[kk + 0][row] = v.x; As[kk + 1][row] = v.y;
            As[kk + 2][row] = v.z; As[kk + 3][row] = v.w;
        }
        // load B tile (64 gate-rows x 16 k) into Bs[k][n]
        {
            int n = tid >> 2, kk = (tid & 3) << 2;
            float4 v = *(const float4*)(W + (size_t)(n0 + n) * K + k0 + kk);
            Bs[kk + 0][n] = v.x; Bs[kk + 1][n] = v.y;
            Bs[kk + 2][n] = v.z; Bs[kk + 3][n] = v.w;
        }
        __syncthreads();
        #pragma unroll
        for (int kk = 0; kk < 16; kk++) {
            float4 a0 = *(const float4*)&As[kk][ty * 8];
            float4 a1 = *(const float4*)&As[kk][ty * 8 + 4];
            float4 bv = *(const float4*)&Bs[kk][tx * 4];
            float ar[8] = {a0.x, a0.y, a0.z, a0.w, a1.x, a1.y, a1.z, a1.w};
            float br[4] = {bv.x, bv.y, bv.z, bv.w};
            #pragma unroll
            for (int i = 0; i < 8; i++)
                #pragma unroll
                for (int j = 0; j < 4; j++)
                    acc[i][j] += ar[i] * br[j];
        }
        __syncthreads();
    }
    float bs[4];
    #pragma unroll
    for (int j = 0; j < 4; j++) {
        int c = n0 + tx * 4 + j;
        bs[j] = bi[c] + bh[c];
    }
    #pragma unroll
    for (int i = 0; i < 8; i++) {
        int m = m0 + ty * 8 + i;
        float4 o;
        o.x = acc[i][0] + bs[0]; o.y = acc[i][1] + bs[1];
        o.z = acc[i][2] + bs[2]; o.w = acc[i][3] + bs[3];
        *(float4*)&g_xproj[dir][m][n0 + tx * 4] = o;
    }
}

// ---------------- persistent recurrent kernel ----------------------------
// grid = 128 blocks x 256 threads. dir = bx&1, block owns j0..j0+3 hidden
// indices (all 4 gates), so the h/c update is block-local. One global
// barrier per timestep per direction (64 arrivals).
__device__ __forceinline__ float sigf(float x) { return 1.f / (1.f + expf(-x)); }

__global__ void __launch_bounds__(256, 1) recurrent_kernel(
    int layer,
    const float* __restrict__ Whf, const float* __restrict__ Whb,
    const float* __restrict__ mask, float* __restrict__ dout)
{
    extern __shared__ float smem[];
    float (*w_sh)[HPAD] = (float(*)[HPAD])smem;                 // 16 x 260
    float (*h_sh)[HPAD] = (float(*)[HPAD])(smem + 16 * HPAD);   // 32 x 260
    float (*g_sh)[16]   = (float(*)[16])  (smem + 48 * HPAD);   // 32 x 16
    float (*c_sh)[4]    = (float(*)[4])   (smem + 48 * HPAD + 512); // 32 x 4

    const int bx  = blockIdx.x;
    const int dir = bx & 1;
    const int j0  = (bx >> 1) * 4;       // 0..252
    const int tid = threadIdx.x;
    const float* Whh = dir ? Whb : Whf;

    // persistent weight load: 16 gate rows (r = gsel*4+jj -> gate gsel*256+j0+jj)
    for (int i = tid; i < 16 * 64; i += 256) {
        int r  = i >> 6;
        int kk = (i & 63) << 2;
        int grow = (r >> 2) * 256 + j0 + (r & 3);
        *(float4*)&w_sh[r][kk] = *(const float4*)&Whh[(size_t)grow * 256 + kk];
    }
    if (tid < 128) c_sh[tid >> 2][tid & 3] = 0.f;

    // dot-product decomposition: k split in 2 halves, thread = (kh, bpair, rpair)
    const int kh = tid >> 7;           // 0/1
    const int u  = tid & 127;
    const int rp = u & 7;              // row pair -> rows 2rp, 2rp+1
    const int bp = u >> 3;             // batch pair -> 2bp, 2bp+1
    const int r0 = rp * 2, r1 = r0 + 1;
    const int b0 = bp * 2, b1 = b0 + 1;
    const int kbase = kh * 128;

    __syncthreads();

    for (int t = 0; t < SS; t++) {
        const int s = dir ? (SS - 1 - t) : t;

        // load previous h into shared (L2-coherent loads; L1 may be stale)
        if (t == 0) {
            for (int i = tid; i < 2048; i += 256) {
                int row = i >> 6, kk = (i & 63) << 2;
                *(float4*)&h_sh[row][kk] = make_float4(0.f, 0.f, 0.f, 0.f);
            }
        } else {
            const float4* src = (const float4*)&g_h[dir][0][0];
            for (int i = tid; i < 2048; i += 256) {
                int row = i >> 6, kk = (i & 63) << 2;
                *(float4*)&h_sh[row][kk] = __ldcg(src + i);
            }
        }

        // prefetch xproj contributions (independent of h)
        float xp00 = 0.f, xp01 = 0.f, xp10 = 0.f, xp11 = 0.f;
        if (kh == 0) {
            const float* xb = &g_xproj[dir][0][0];
            size_t mA = (size_t)(s * 32 + b0) * 1024;
            size_t mB = (size_t)(s * 32 + b1) * 1024;
            int gr0 = (r0 >> 2) * 256 + j0 + (r0 & 3);
            int gr1 = (r1 >> 2) * 256 + j0 + (r1 & 3);
            xp00 = xb[mA + gr0]; xp01 = xb[mA + gr1];
            xp10 = xb[mB + gr0]; xp11 = xb[mB + gr1];
        }
        __syncthreads();

        // partial dots over this thread's k-half
        float a00 = 0.f, a01 = 0.f, a10 = 0.f, a11 = 0.f;
        #pragma unroll 8
        for (int k4 = 0; k4 < 32; k4++) {
            int kk = kbase + k4 * 4;
            float4 hA = *(const float4*)&h_sh[b0][kk];
            float4 hB = *(const float4*)&h_sh[b1][kk];
            float4 wA = *(const float4*)&w_sh[r0][kk];
            float4 wB = *(const float4*)&w_sh[r1][kk];
            a00 += hA.x*wA.x + hA.y*wA.y + hA.z*wA.z + hA.w*wA.w;
            a01 += hA.x*wB.x + hA.y*wB.y + hA.z*wB.z + hA.w*wB.w;
            a10 += hB.x*wA.x + hB.y*wA.y + hB.z*wA.z + hB.w*wA.w;
            a11 += hB.x*wB.x + hB.y*wB.y + hB.z*wB.z + hB.w*wB.w;
        }
        if (kh == 1) {
            g_sh[b0][r0] = a00; g_sh[b0][r1] = a01;
            g_sh[b1][r0] = a10; g_sh[b1][r1] = a11;
        }
        __syncthreads();
        if (kh == 0) {
            g_sh[b0][r0] += a00 + xp00; g_sh[b0][r1] += a01 + xp01;
            g_sh[b1][r0] += a10 + xp10; g_sh[b1][r1] += a11 + xp11;
        }
        __syncthreads();

        // gate nonlinearities + state update (block-local: owns j0..j0+3)
        if (tid < 128) {
            int b = tid >> 2, jj = tid & 3;
            float iv = sigf (g_sh[b][0  + jj]);
            float fv = sigf (g_sh[b][4  + jj]);
            float gv = tanhf(g_sh[b][8  + jj]);
            float ov = sigf (g_sh[b][12 + jj]);
            float c = fv * c_sh[b][jj] + iv * gv;
            float mt = mask[b * SS + s];
            c *= mt;                              // c0 = 0
            float h = ov * tanhf(c) * mt;         // h0 = 0
            c_sh[b][jj] = c;
            g_h[dir][b][j0 + jj] = h;
            if (layer == 0)
                g_out0[s * 32 + b][dir * 256 + j0 + jj] = h;
            else
                dout[((size_t)b * SS + s) * 512 + dir * 256 + j0 + jj] = h;
            if (t == SS - 1) {
                size_t off = (size_t)layer * BB * 512 + (size_t)b * 512 + dir * 256 + j0 + jj;
                dout[HN_OFF + off] = h;
                dout[CN_OFF + off] = c;
            }
        }

        // inter-block barrier (per direction, per step)
        if (t < SS - 1) {
            __threadfence();
            __syncthreads();
            if (tid == 0) {
                atomicAdd(&g_cnt[layer][dir][t], 1);
                volatile int* p = &g_cnt[layer][dir][t];
                while (*p < NBLK_DIR) __nanosleep(64);
            }
            __syncthreads();
            __threadfence();
        }
    }
}

// ---------------- launch ------------------------------------------------
extern "C" void kernel_launch(void* const* d_in, const int* in_sizes, int n_in,
                              void* d_out, int out_size)
{
    const float* inputs  = (const float*)d_in[0];
    const float* mask    = (const float*)d_in[1];
    const float* l0f_Wih = (const float*)d_in[2];
    const float* l0f_Whh = (const float*)d_in[3];
    const float* l0f_bih = (const float*)d_in[4];
    const float* l0f_bhh = (const float*)d_in[5];
    const float* l0b_Wih = (const float*)d_in[6];
    const float* l0b_Whh = (const float*)d_in[7];
    const float* l0b_bih = (const float*)d_in[8];
    const float* l0b_bhh = (const float*)d_in[9];
    const float* l1f_Wih = (const float*)d_in[10];
    const float* l1f_Whh = (const float*)d_in[11];
    const float* l1f_bih = (const float*)d_in[12];
    const float* l1f_bhh = (const float*)d_in[13];
    const float* l1b_Wih = (const float*)d_in[14];
    const float* l1b_Whh = (const float*)d_in[15];
    const float* l1b_bih = (const float*)d_in[16];
    const float* l1b_bhh = (const float*)d_in[17];
    float* out = (float*)d_out;

    const int shmem = (48 * HPAD + 512 + 128) * 4;   // 52480 bytes
    cudaFuncSetAttribute(recurrent_kernel,
                         cudaFuncAttributeMaxDynamicSharedMemorySize, shmem);

    reset_kernel<<<16, 256>>>();

    dim3 g(16, 256, 2);   // N/64, M/128, dirs
    xproj_kernel<<<g, 256>>>(inputs, 0, 256,
                             l0f_Wih, l0b_Wih, l0f_bih, l0f_bhh, l0b_bih, l0b_bhh);
    recurrent_kernel<<<128, 256, shmem>>>(0, l0f_Whh, l0b_Whh, mask, out);

    xproj_kernel<<<g, 256>>>(nullptr, 1, 512,
                             l1f_Wih, l1b_Wih, l1f_bih, l1f_bhh, l1b_bih, l1b_bhh);
    recurrent_kernel<<<128, 256, shmem>>>(1, l1f_Whh, l1b_Whh, mask, out);
}